// round 15
// baseline (speedup 1.0000x reference)
#include <cuda_runtime.h>
#include <cuda_bf16.h>
#include <math.h>

#define HD   1024
#define LSEQ 256
#define VOUT 32000
#define H3   (3*HD)
#define START_ID 1

// ---------------- device scratch (static allocation only) ----------------
__device__ __align__(16) __nv_bfloat16 g_encWh[H3*HD];     // 6 MB
__device__ __align__(16) __nv_bfloat16 g_decWi[H3*HD];     // 6 MB
__device__ __align__(16) __nv_bfloat16 g_decWh[H3*HD];     // 6 MB
__device__ __align__(16) __nv_bfloat16 g_attnWh[LSEQ*HD];  // 0.5 MB  attn_W[:, H:]
__device__ __align__(16) __nv_bfloat16 g_combWx[HD*HD];    // 2 MB    comb_W[:, H:]
__device__ __align__(16) __nv_bfloat16 g_encT[HD*LSEQ];    // enc_outs^T (bf16)
__device__ __align__(16) float g_h[HD];
__device__ __align__(16) float g_scores[LSEQ];
__device__ __align__(16) float g_ctx[HD];
__device__ __align__(16) float g_c[HD];
__device__ __align__(16) float g_encgi[LSEQ*H3];           // enc_Wi@x + bi
__device__ __align__(16) float g_attnpre[LSEQ*LSEQ];       // attn_W[:,:H]@e + attn_b
__device__ __align__(16) float g_combpre[LSEQ*HD];         // comb_W[:,:H]@e + comb_b
__device__ __align__(16) float g_H2[LSEQ*HD];              // decoder hidden states
__device__ __align__(16) float g_logits[LSEQ*VOUT];        // 32.8 MB
__device__ float g_nll[LSEQ];
__device__ int   g_decin[LSEQ];
__device__ unsigned long long g_bar;                        // monotone grid barrier

// ---------------- helpers ----------------
struct F8 { float v[8]; };

__device__ __forceinline__ F8 ldbf8(const __nv_bfloat16* p) {
    uint4 u = *reinterpret_cast<const uint4*>(p);
    F8 r; float2 f;
    f = __bfloat1622float2(*reinterpret_cast<const __nv_bfloat162*>(&u.x)); r.v[0]=f.x; r.v[1]=f.y;
    f = __bfloat1622float2(*reinterpret_cast<const __nv_bfloat162*>(&u.y)); r.v[2]=f.x; r.v[3]=f.y;
    f = __bfloat1622float2(*reinterpret_cast<const __nv_bfloat162*>(&u.z)); r.v[4]=f.x; r.v[5]=f.y;
    f = __bfloat1622float2(*reinterpret_cast<const __nv_bfloat162*>(&u.w)); r.v[6]=f.x; r.v[7]=f.y;
    return r;
}
__device__ __forceinline__ F8 lds8(const float* s) {
    float4 a = *reinterpret_cast<const float4*>(s);
    float4 b = *reinterpret_cast<const float4*>(s + 4);
    F8 r; r.v[0]=a.x; r.v[1]=a.y; r.v[2]=a.z; r.v[3]=a.w;
          r.v[4]=b.x; r.v[5]=b.y; r.v[6]=b.z; r.v[7]=b.w;
    return r;
}
__device__ __forceinline__ float dot8(const F8& w, const F8& x) {
    float s = 0.f;
#pragma unroll
    for (int q = 0; q < 8; ++q) s = fmaf(w.v[q], x.v[q], s);
    return s;
}
__device__ __forceinline__ float warp_sum(float v) {
#pragma unroll
    for (int o = 16; o; o >>= 1) v += __shfl_xor_sync(0xffffffffu, v, o);
    return v;
}
__device__ __forceinline__ float warp_max(float v) {
#pragma unroll
    for (int o = 16; o; o >>= 1) v = fmaxf(v, __shfl_xor_sync(0xffffffffu, v, o));
    return v;
}
__device__ __forceinline__ float block_sum(float v, float* red) {
    int lane = threadIdx.x & 31, wid = threadIdx.x >> 5;
    v = warp_sum(v);
    if (lane == 0) red[wid] = v;
    __syncthreads();
    float s = (threadIdx.x < (blockDim.x >> 5)) ? red[threadIdx.x] : 0.f;
    if (wid == 0) { s = warp_sum(s); if (lane == 0) red[8] = s; }
    __syncthreads();
    float r = red[8];
    __syncthreads();
    return r;
}
__device__ __forceinline__ float block_max(float v, float* red) {
    int lane = threadIdx.x & 31, wid = threadIdx.x >> 5;
    v = warp_max(v);
    if (lane == 0) red[wid] = v;
    __syncthreads();
    float s = (threadIdx.x < (blockDim.x >> 5)) ? red[threadIdx.x] : -1e30f;
    if (wid == 0) { s = warp_max(s); if (lane == 0) red[8] = s; }
    __syncthreads();
    float r = red[8];
    __syncthreads();
    return r;
}
__device__ __forceinline__ float sigmoidf(float x) { return 1.f / (1.f + __expf(-x)); }

// Race-free grid barrier: monotone counter, no reset needed across graph replays.
// All N arrivals of one episode compute the same target = (old/N + 1)*N.
__device__ __forceinline__ void grid_sync(unsigned nb) {
    __syncthreads();
    if (threadIdx.x == 0) {
        __threadfence();
        unsigned long long old = atomicAdd(&g_bar, 1ULL);
        unsigned long long target = (old / nb + 1ULL) * (unsigned long long)nb;
        while (atomicAdd(&g_bar, 0ULL) < target) { __nanosleep(64); }
        __threadfence();
    }
    __syncthreads();
}

// ---------------- prep: build dec_in ids, zero h0, convert weights to bf16 ----------------
__global__ void k_prep(const int* __restrict__ tgt,
                       const float* __restrict__ eWh, const float* __restrict__ dWi,
                       const float* __restrict__ dWh, const float* __restrict__ aW,
                       const float* __restrict__ cW) {
    int gid = blockIdx.x * blockDim.x + threadIdx.x;
    int stride = gridDim.x * blockDim.x;
    for (int i = gid; i < H3 * HD; i += stride) {
        g_encWh[i] = __float2bfloat16(eWh[i]);
        g_decWi[i] = __float2bfloat16(dWi[i]);
        g_decWh[i] = __float2bfloat16(dWh[i]);
    }
    for (int i = gid; i < LSEQ * HD; i += stride) {
        int l = i >> 10, j = i & 1023;
        g_attnWh[i] = __float2bfloat16(aW[l * 2 * HD + HD + j]);
    }
    for (int i = gid; i < HD * HD; i += stride) {
        int r = i >> 10, k = i & 1023;
        g_combWx[i] = __float2bfloat16(cW[r * 2 * HD + HD + k]);
    }
    if (gid < LSEQ) g_decin[gid] = (gid == 0) ? START_ID : tgt[gid - 1];
    if (gid < HD)   g_h[gid] = 0.f;
}

// ---------------- generic NT GEMM: C[m][n] = sum_k A[row(m)][k]*B[n][k] + bias[n] ----------------
// M multiple of 64, N multiple of 64, K = 1024. Optional row gather on A.
__global__ __launch_bounds__(256) void gemm_nt(const float* __restrict__ A, int lda,
                                               const int* __restrict__ rowmap,
                                               const float* __restrict__ B, int ldb,
                                               const float* __restrict__ bias,
                                               float* __restrict__ C, int ldc) {
    __shared__ __align__(16) float Asm[16][64];
    __shared__ __align__(16) float Bsm[16][64];
    const int tid = threadIdx.x;
    const int r  = tid >> 2;   // 0..63
    const int c4 = tid & 3;    // 0..3
    const int ty = tid >> 4, tx = tid & 15;
    const int m0 = blockIdx.y * 64, n0 = blockIdx.x * 64;
    int arow = m0 + r;
    if (rowmap) arow = rowmap[arow];
    const float* Aptr = A + (size_t)arow * lda + c4 * 4;
    const float* Bptr = B + (size_t)(n0 + r) * ldb + c4 * 4;
    float acc[4][4] = {};
    for (int k0 = 0; k0 < 1024; k0 += 16) {
        float4 av = *reinterpret_cast<const float4*>(Aptr + k0);
        float4 bv = *reinterpret_cast<const float4*>(Bptr + k0);
        Asm[c4*4+0][r] = av.x; Asm[c4*4+1][r] = av.y; Asm[c4*4+2][r] = av.z; Asm[c4*4+3][r] = av.w;
        Bsm[c4*4+0][r] = bv.x; Bsm[c4*4+1][r] = bv.y; Bsm[c4*4+2][r] = bv.z; Bsm[c4*4+3][r] = bv.w;
        __syncthreads();
#pragma unroll
        for (int kk = 0; kk < 16; ++kk) {
            float4 a = *reinterpret_cast<const float4*>(&Asm[kk][ty * 4]);
            float4 b = *reinterpret_cast<const float4*>(&Bsm[kk][tx * 4]);
            acc[0][0]=fmaf(a.x,b.x,acc[0][0]); acc[0][1]=fmaf(a.x,b.y,acc[0][1]);
            acc[0][2]=fmaf(a.x,b.z,acc[0][2]); acc[0][3]=fmaf(a.x,b.w,acc[0][3]);
            acc[1][0]=fmaf(a.y,b.x,acc[1][0]); acc[1][1]=fmaf(a.y,b.y,acc[1][1]);
            acc[1][2]=fmaf(a.y,b.z,acc[1][2]); acc[1][3]=fmaf(a.y,b.w,acc[1][3]);
            acc[2][0]=fmaf(a.z,b.x,acc[2][0]); acc[2][1]=fmaf(a.z,b.y,acc[2][1]);
            acc[2][2]=fmaf(a.z,b.z,acc[2][2]); acc[2][3]=fmaf(a.z,b.w,acc[2][3]);
            acc[3][0]=fmaf(a.w,b.x,acc[3][0]); acc[3][1]=fmaf(a.w,b.y,acc[3][1]);
            acc[3][2]=fmaf(a.w,b.z,acc[3][2]); acc[3][3]=fmaf(a.w,b.w,acc[3][3]);
        }
        __syncthreads();
    }
#pragma unroll
    for (int i = 0; i < 4; ++i) {
        int m = m0 + ty * 4 + i;
#pragma unroll
        for (int j = 0; j < 4; ++j) {
            int n = n0 + tx * 4 + j;
            C[(size_t)m * ldc + n] = acc[i][j] + bias[n];
        }
    }
}

// ---------------- encoder scan (persistent, 1 barrier/step) ----------------
__global__ __launch_bounds__(256, 1) void k_encoder(const float* __restrict__ enc_bh, unsigned nb) {
    __shared__ __align__(16) float sh_h[HD];
    const int tid = threadIdx.x;
    const int gw  = (blockIdx.x * 256 + tid) >> 5;
    const int lane = tid & 31;
    for (int t = 0; t < LSEQ; ++t) {
        for (int i = tid; i < HD; i += 256) sh_h[i] = __ldcg(&g_h[i]);
        __syncthreads();
        if (gw < HD) {
            const __nv_bfloat16* wr = g_encWh + (size_t)gw * HD;
            const __nv_bfloat16* wz = wr + (size_t)HD * HD;
            const __nv_bfloat16* wn = wz + (size_t)HD * HD;
            float ar = 0.f, az = 0.f, an = 0.f;
#pragma unroll
            for (int it = 0; it < 4; ++it) {
                int base = it * 256 + lane * 8;
                F8 h8 = lds8(&sh_h[base]);
                ar += dot8(ldbf8(wr + base), h8);
                az += dot8(ldbf8(wz + base), h8);
                an += dot8(ldbf8(wn + base), h8);
            }
            ar = warp_sum(ar); az = warp_sum(az); an = warp_sum(an);
            if (lane == 0) {
                const float* gi = g_encgi + (size_t)t * H3;
                float ghr = ar + enc_bh[gw];
                float ghz = az + enc_bh[HD + gw];
                float ghn = an + enc_bh[2 * HD + gw];
                float rg = sigmoidf(gi[gw] + ghr);
                float zg = sigmoidf(gi[HD + gw] + ghz);
                float ng = tanhf(gi[2 * HD + gw] + rg * ghn);
                float h2 = (1.f - zg) * ng + zg * sh_h[gw];
                __stcg(&g_h[gw], h2);
                g_encT[(size_t)gw * LSEQ + t] = __float2bfloat16(h2);
            }
        }
        grid_sync(nb);
    }
}

// ---------------- decoder scan (persistent, 4 barriers/step) ----------------
__global__ __launch_bounds__(256, 1) void k_decoder(const float* __restrict__ dec_bi,
                                                    const float* __restrict__ dec_bh,
                                                    unsigned nb) {
    __shared__ __align__(16) float sh_h[HD];
    __shared__ __align__(16) float sh_x[HD];
    __shared__ __align__(16) float sh_c[HD];
    __shared__ __align__(16) float sh_a[LSEQ];
    __shared__ float red[9];
    const int tid = threadIdx.x;
    const int gw  = (blockIdx.x * 256 + tid) >> 5;
    const int lane = tid & 31;
    for (int t = 0; t < LSEQ; ++t) {
        for (int i = tid; i < HD; i += 256) sh_h[i] = __ldcg(&g_h[i]);
        __syncthreads();
        // --- stage A: attention scores(h) ---
        if (gw < LSEQ) {
            const __nv_bfloat16* wa = g_attnWh + (size_t)gw * HD;
            float acc = 0.f;
#pragma unroll
            for (int it = 0; it < 4; ++it) {
                int base = it * 256 + lane * 8;
                acc += dot8(ldbf8(wa + base), lds8(&sh_h[base]));
            }
            acc = warp_sum(acc);
            if (lane == 0) __stcg(&g_scores[gw], acc + g_attnpre[t * LSEQ + gw]);
        }
        grid_sync(nb);
        // --- stage B: softmax (redundant per block) + ctx ---
        {
            float sc = __ldcg(&g_scores[tid]);
            float mx = block_max(sc, red);
            float e  = __expf(sc - mx);
            float sm = block_sum(e, red);
            sh_a[tid] = e / sm;
        }
        __syncthreads();
        if (gw < HD) {
            const __nv_bfloat16* er = g_encT + (size_t)gw * LSEQ;
            int base = lane * 8;
            float acc = dot8(ldbf8(er + base), lds8(&sh_a[base]));
            acc = warp_sum(acc);
            if (lane == 0) __stcg(&g_ctx[gw], acc);
        }
        grid_sync(nb);
        // --- stage C: c = relu(comb_pre + combWx @ ctx) ---
        for (int i = tid; i < HD; i += 256) sh_x[i] = __ldcg(&g_ctx[i]);
        __syncthreads();
        if (gw < HD) {
            const __nv_bfloat16* wc = g_combWx + (size_t)gw * HD;
            float acc = 0.f;
#pragma unroll
            for (int it = 0; it < 4; ++it) {
                int base = it * 256 + lane * 8;
                acc += dot8(ldbf8(wc + base), lds8(&sh_x[base]));
            }
            acc = warp_sum(acc);
            if (lane == 0) __stcg(&g_c[gw], fmaxf(acc + g_combpre[t * HD + gw], 0.f));
        }
        grid_sync(nb);
        // --- stage D: GRU cell (gi on c, gh on h), write h2 ---
        for (int i = tid; i < HD; i += 256) sh_c[i] = __ldcg(&g_c[i]);
        __syncthreads();
        if (gw < HD) {
            const __nv_bfloat16* wir = g_decWi + (size_t)gw * HD;
            const __nv_bfloat16* wiz = wir + (size_t)HD * HD;
            const __nv_bfloat16* win = wiz + (size_t)HD * HD;
            const __nv_bfloat16* whr = g_decWh + (size_t)gw * HD;
            const __nv_bfloat16* whz = whr + (size_t)HD * HD;
            const __nv_bfloat16* whn = whz + (size_t)HD * HD;
            float air = 0.f, aiz = 0.f, ain = 0.f, ahr = 0.f, ahz = 0.f, ahn = 0.f;
#pragma unroll
            for (int it = 0; it < 4; ++it) {
                int base = it * 256 + lane * 8;
                F8 c8 = lds8(&sh_c[base]);
                F8 h8 = lds8(&sh_h[base]);
                air += dot8(ldbf8(wir + base), c8);
                aiz += dot8(ldbf8(wiz + base), c8);
                ain += dot8(ldbf8(win + base), c8);
                ahr += dot8(ldbf8(whr + base), h8);
                ahz += dot8(ldbf8(whz + base), h8);
                ahn += dot8(ldbf8(whn + base), h8);
            }
            air = warp_sum(air); aiz = warp_sum(aiz); ain = warp_sum(ain);
            ahr = warp_sum(ahr); ahz = warp_sum(ahz); ahn = warp_sum(ahn);
            if (lane == 0) {
                float gir = air + dec_bi[gw];
                float giz = aiz + dec_bi[HD + gw];
                float gin = ain + dec_bi[2 * HD + gw];
                float ghr = ahr + dec_bh[gw];
                float ghz = ahz + dec_bh[HD + gw];
                float ghn = ahn + dec_bh[2 * HD + gw];
                float rg = sigmoidf(gir + ghr);
                float zg = sigmoidf(giz + ghz);
                float ng = tanhf(gin + rg * ghn);
                float h2 = (1.f - zg) * ng + zg * sh_h[gw];
                __stcg(&g_h[gw], h2);
                g_H2[(size_t)t * HD + gw] = h2;
            }
        }
        grid_sync(nb);
    }
}

// ---------------- per-row logsumexp -> nll ----------------
__global__ __launch_bounds__(256) void k_nll(const int* __restrict__ tgt) {
    __shared__ float red[9];
    int t = blockIdx.x;
    const float* row = g_logits + (size_t)t * VOUT;
    float m = -1e30f;
    for (int v = threadIdx.x; v < VOUT; v += 256) m = fmaxf(m, row[v]);
    m = block_max(m, red);
    float s = 0.f;
    for (int v = threadIdx.x; v < VOUT; v += 256) s += __expf(row[v] - m);
    s = block_sum(s, red);
    if (threadIdx.x == 0) g_nll[t] = m + logf(s) - row[tgt[t]];
}

__global__ __launch_bounds__(256) void k_final(float* __restrict__ out) {
    __shared__ float sm[256];
    sm[threadIdx.x] = g_nll[threadIdx.x];
    __syncthreads();
    for (int o = 128; o; o >>= 1) {
        if (threadIdx.x < o) sm[threadIdx.x] += sm[threadIdx.x + o];
        __syncthreads();
    }
    if (threadIdx.x == 0) out[0] = sm[0];
}

// ---------------- launch ----------------
extern "C" void kernel_launch(void* const* d_in, const int* in_sizes, int n_in,
                              void* d_out, int out_size) {
    const int*   input_ids  = (const int*)d_in[0];
    const int*   target_ids = (const int*)d_in[1];
    const float* enc_emb = (const float*)d_in[2];
    const float* enc_Wi  = (const float*)d_in[3];
    const float* enc_Wh  = (const float*)d_in[4];
    const float* enc_bi  = (const float*)d_in[5];
    const float* enc_bh  = (const float*)d_in[6];
    const float* dec_emb = (const float*)d_in[7];
    const float* dec_Wi  = (const float*)d_in[8];
    const float* dec_Wh  = (const float*)d_in[9];
    const float* dec_bi  = (const float*)d_in[10];
    const float* dec_bh  = (const float*)d_in[11];
    const float* attn_W  = (const float*)d_in[12];
    const float* attn_b  = (const float*)d_in[13];
    const float* comb_W  = (const float*)d_in[14];
    const float* comb_b  = (const float*)d_in[15];
    const float* out_W   = (const float*)d_in[16];
    const float* out_b   = (const float*)d_in[17];

    int dev = 0, nsm = 0;
    cudaGetDevice(&dev);
    cudaDeviceGetAttribute(&nsm, cudaDevAttrMultiProcessorCount, dev);
    if (nsm < 128) nsm = 128;  // safety floor for warp coverage (need >=128 blocks * 8 warps)
    unsigned NB = (unsigned)nsm;

    void *p_encgi, *p_attnpre, *p_combpre, *p_H2, *p_logits, *p_decin;
    cudaGetSymbolAddress(&p_encgi,   g_encgi);
    cudaGetSymbolAddress(&p_attnpre, g_attnpre);
    cudaGetSymbolAddress(&p_combpre, g_combpre);
    cudaGetSymbolAddress(&p_H2,      g_H2);
    cudaGetSymbolAddress(&p_logits,  g_logits);
    cudaGetSymbolAddress(&p_decin,   g_decin);

    // 1) convert weights to bf16, build dec_in ids, zero h0
    k_prep<<<1024, 256>>>(target_ids, enc_Wh, dec_Wi, dec_Wh, attn_W, comb_W);
    // 2) batched precomputes
    gemm_nt<<<dim3(H3 / 64, LSEQ / 64), 256>>>(enc_emb, HD, input_ids, enc_Wi, HD,
                                               enc_bi, (float*)p_encgi, H3);
    gemm_nt<<<dim3(LSEQ / 64, LSEQ / 64), 256>>>(dec_emb, HD, (const int*)p_decin, attn_W, 2 * HD,
                                                 attn_b, (float*)p_attnpre, LSEQ);
    gemm_nt<<<dim3(HD / 64, LSEQ / 64), 256>>>(dec_emb, HD, (const int*)p_decin, comb_W, 2 * HD,
                                               comb_b, (float*)p_combpre, HD);
    // 3) sequential scans (persistent kernels)
    k_encoder<<<NB, 256>>>(enc_bh, NB);
    k_decoder<<<NB, 256>>>(dec_bi, dec_bh, NB);
    // 4) big output projection, batched over all 256 steps
    gemm_nt<<<dim3(VOUT / 64, LSEQ / 64), 256>>>((const float*)p_H2, HD, nullptr, out_W, HD,
                                                 out_b, (float*)p_logits, VOUT);
    // 5) per-row logsumexp -> nll, then deterministic sum
    k_nll<<<LSEQ, 256>>>(target_ids);
    k_final<<<1, 256>>>((float*)d_out);
}